// round 14
// baseline (speedup 1.0000x reference)
#include <cuda_runtime.h>
#include <math.h>
#include <stdint.h>

#define N_NODES 50000
#define F_IN 128
#define HID 256
#define NCLS 40
#define N_EDGES 600000
#define BN_EPS 1e-5f
#define SCAN_BLK 1024
#define N_SCAN_BLOCKS ((N_NODES + SCAN_BLK - 1) / SCAN_BLK)   // 49

// Scratch (static device globals -- no runtime allocation allowed)
__device__ float g_agg1[N_NODES * F_IN];  // gather result, tf32-rounded
__device__ float g_h1[N_NODES * HID];     // relu(BN1(...)), tf32-rounded
__device__ float g_z[N_NODES * NCLS];     // h1 @ W2 (pre-aggregation logits)
__device__ float g_w1tf[F_IN * HID];      // W1 pre-rounded to tf32
__device__ float g_w2tf[HID * NCLS];      // W2 pre-rounded to tf32
__device__ float g_bn0s[F_IN];            // BN0 scale  = gamma/sqrt(var+eps)
__device__ float g_bn0t[F_IN];            // BN0 shift  = beta - mean*scale
// CSR-by-dst scratch
__device__ int g_deg[N_NODES];
__device__ int g_roff[N_NODES];           // exclusive offsets
__device__ int g_cur[N_NODES];            // fill cursors
__device__ int g_part[64];                // per-block scan partials
__device__ int g_eidx[N_EDGES];           // src ids grouped by dst

__device__ __forceinline__ int clamp_idx(int i) {
    i = i < 0 ? 0 : i;
    return i >= N_NODES ? N_NODES - 1 : i;
}

// Round-to-nearest f32 -> tf32 (kept in 32-bit container)
__device__ __forceinline__ unsigned tf32r(float x) {
    unsigned r;
    asm("cvt.rna.tf32.f32 %0, %1;" : "=r"(r) : "f"(x));
    return r;
}

// D += A*B for one m16n8k8 tf32 tile
__device__ __forceinline__ void mma_tf32(float* d, const unsigned* a, const unsigned* b) {
    asm volatile(
        "mma.sync.aligned.m16n8k8.row.col.f32.tf32.tf32.f32 "
        "{%0,%1,%2,%3}, {%4,%5,%6,%7}, {%8,%9}, {%0,%1,%2,%3};"
        : "+f"(d[0]), "+f"(d[1]), "+f"(d[2]), "+f"(d[3])
        : "r"(a[0]), "r"(a[1]), "r"(a[2]), "r"(a[3]), "r"(b[0]), "r"(b[1]));
}

__device__ __forceinline__ void cp_async16(uint32_t saddr, const void* gptr, int sz) {
    asm volatile("cp.async.cg.shared.global [%0], [%1], 16, %2;"
                 :: "r"(saddr), "l"(gptr), "r"(sz) : "memory");
}
__device__ __forceinline__ void cp_commit() {
    asm volatile("cp.async.commit_group;" ::: "memory");
}
template <int N>
__device__ __forceinline__ void cp_wait() {
    asm volatile("cp.async.wait_group %0;" :: "n"(N) : "memory");
}
__device__ __forceinline__ uint32_t smem_u32(const void* p) {
    return (uint32_t)__cvta_generic_to_shared(p);
}

// ---------------------------------------------------------------------------
// K0: weight pre-rounding to tf32 + BN0 affine precompute + deg zeroing
// ---------------------------------------------------------------------------
__global__ void convert_w_kernel(const float* __restrict__ W1,
                                 const float* __restrict__ W2,
                                 const float* __restrict__ bn0g,
                                 const float* __restrict__ bn0b,
                                 const float* __restrict__ bn0m,
                                 const float* __restrict__ bn0v) {
    int i = blockIdx.x * blockDim.x + threadIdx.x;
    if (i < F_IN * HID) g_w1tf[i] = __uint_as_float(tf32r(W1[i]));
    if (i < HID * NCLS) g_w2tf[i] = __uint_as_float(tf32r(W2[i]));
    if (i < F_IN) {
        float s = bn0g[i] * rsqrtf(bn0v[i] + BN_EPS);
        g_bn0s[i] = s;
        g_bn0t[i] = bn0b[i] - bn0m[i] * s;
    }
    if (i < N_NODES) g_deg[i] = 0;
}

// ---------------------------------------------------------------------------
// CSR build: hist -> block scan -> partial scan -> add -> fill
// ---------------------------------------------------------------------------
__global__ void hist_kernel(const int* __restrict__ dst) {
    int e = blockIdx.x * blockDim.x + threadIdx.x;
    if (e >= N_EDGES) return;
    atomicAdd(&g_deg[clamp_idx(__ldg(dst + e))], 1);
}

__global__ void scan_block_kernel() {
    __shared__ int wsum[32];
    int tid = threadIdx.x;
    int i = blockIdx.x * SCAN_BLK + tid;
    int lane = tid & 31, wid = tid >> 5;
    int v = (i < N_NODES) ? g_deg[i] : 0;
    int s = v;
#pragma unroll
    for (int off = 1; off < 32; off <<= 1) {
        int u = __shfl_up_sync(0xFFFFFFFFu, s, off);
        if (lane >= off) s += u;
    }
    if (lane == 31) wsum[wid] = s;
    __syncthreads();
    if (wid == 0) {
        int ws = wsum[lane];
        int t = ws;
#pragma unroll
        for (int off = 1; off < 32; off <<= 1) {
            int u = __shfl_up_sync(0xFFFFFFFFu, t, off);
            if (lane >= off) t += u;
        }
        wsum[lane] = t - ws;                  // exclusive warp prefix
        if (lane == 31) g_part[blockIdx.x] = t;  // block total
    }
    __syncthreads();
    if (i < N_NODES) g_roff[i] = s - v + wsum[wid];
}

__global__ void scan_part_kernel() {
    __shared__ int buf[64];
    int tid = threadIdx.x;
    int v = (tid < N_SCAN_BLOCKS) ? g_part[tid] : 0;
    buf[tid] = v;
    __syncthreads();
#pragma unroll
    for (int off = 1; off < 64; off <<= 1) {
        int t = (tid >= off) ? buf[tid - off] : 0;
        __syncthreads();
        buf[tid] += t;
        __syncthreads();
    }
    if (tid < N_SCAN_BLOCKS) g_part[tid] = buf[tid] - v;  // exclusive
}

__global__ void scan_add_kernel() {
    int i = blockIdx.x * blockDim.x + threadIdx.x;
    if (i >= N_NODES) return;
    int r = g_roff[i] + g_part[i / SCAN_BLK];
    g_roff[i] = r;
    g_cur[i] = r;
}

__global__ void fill_kernel(const int* __restrict__ src, const int* __restrict__ dst) {
    int e = blockIdx.x * blockDim.x + threadIdx.x;
    if (e >= N_EDGES) return;
    int d = clamp_idx(__ldg(dst + e));
    int s = clamp_idx(__ldg(src + e));
    int p = atomicAdd(&g_cur[d], 1);
    g_eidx[p] = s;
}

// ---------------------------------------------------------------------------
// K2: gather aggregation fused with BN0 (affine). One warp per node.
//     agg1[i] = (x_i + sum_j x_j) * s + (1+deg)*t, tf32-rounded.
// ---------------------------------------------------------------------------
__global__ void agg128_kernel(const float4* __restrict__ x) {
    int node = (blockIdx.x * blockDim.x + threadIdx.x) >> 5;
    if (node >= N_NODES) return;
    int lane = threadIdx.x & 31;
    int c = lane * 4;
    float4 acc = x[(size_t)node * 32 + lane];
    int beg = g_roff[node];
    int end = (node + 1 < N_NODES) ? g_roff[node + 1] : N_EDGES;
    int j = beg;
    for (; j + 1 < end; j += 2) {
        int s0 = __ldg(g_eidx + j);
        int s1 = __ldg(g_eidx + j + 1);
        float4 v0 = x[(size_t)s0 * 32 + lane];
        float4 v1 = x[(size_t)s1 * 32 + lane];
        acc.x += v0.x; acc.y += v0.y; acc.z += v0.z; acc.w += v0.w;
        acc.x += v1.x; acc.y += v1.y; acc.z += v1.z; acc.w += v1.w;
    }
    if (j < end) {
        int s0 = __ldg(g_eidx + j);
        float4 v0 = x[(size_t)s0 * 32 + lane];
        acc.x += v0.x; acc.y += v0.y; acc.z += v0.z; acc.w += v0.w;
    }
    float cnt = (float)(1 + end - beg);
    float4 o;
    o.x = __uint_as_float(tf32r(acc.x * __ldg(g_bn0s + c + 0) + cnt * __ldg(g_bn0t + c + 0)));
    o.y = __uint_as_float(tf32r(acc.y * __ldg(g_bn0s + c + 1) + cnt * __ldg(g_bn0t + c + 1)));
    o.z = __uint_as_float(tf32r(acc.z * __ldg(g_bn0s + c + 2) + cnt * __ldg(g_bn0t + c + 2)));
    o.w = __uint_as_float(tf32r(acc.w * __ldg(g_bn0s + c + 3) + cnt * __ldg(g_bn0t + c + 3)));
    ((float4*)(g_agg1 + (size_t)node * F_IN))[lane] = o;
}

// ---------------------------------------------------------------------------
// K3: GEMM1 [50000,128]x[128,256] + bias + BN1 + ReLU -> g_h1 (tf32-rounded).
//     TF32 mma, cp.async 2-stage pipeline (R12 proven). CTA 128x128, BK=16.
// ---------------------------------------------------------------------------
__global__ void __launch_bounds__(256)
gemm1_kernel(const float* __restrict__ b1,
             const float* __restrict__ bg, const float* __restrict__ bb,
             const float* __restrict__ bm, const float* __restrict__ bv) {
    __shared__ __align__(16) unsigned sA[2][128][20];   // [buf][m][k]
    __shared__ __align__(16) unsigned sB[2][16][136];   // [buf][k][n]
    int tid = threadIdx.x;
    int warp = tid >> 5, lane = tid & 31;
    int wm = warp >> 2, wn = warp & 3;
    int gq = lane >> 2, tg = lane & 3;
    int block_m = blockIdx.x * 128;
    int block_n = blockIdx.y * 128;

    int a_row[2], a_c4[2], a_sz[2];
    const float* a_gp0[2];
#pragma unroll
    for (int i = 0; i < 2; i++) {
        int f4 = tid + i * 256;          // 0..511
        a_row[i] = f4 >> 2;              // 0..127
        a_c4[i] = f4 & 3;                // 0..3
        int gr = block_m + a_row[i];
        a_sz[i] = (gr < N_NODES) ? 16 : 0;
        a_gp0[i] = g_agg1 + (size_t)min(gr, N_NODES - 1) * F_IN + a_c4[i] * 4;
    }
    int b_k[2], b_c4[2];
#pragma unroll
    for (int i = 0; i < 2; i++) {
        int f4 = tid + i * 256;
        b_k[i] = f4 >> 5;                // 0..15
        b_c4[i] = f4 & 31;               // 0..31
    }

#define G1_ISSUE(chunk, buf)                                                      \
    {                                                                             \
        int kk_ = (chunk) * 16;                                                   \
        _Pragma("unroll")                                                         \
        for (int i = 0; i < 2; i++)                                               \
            cp_async16(smem_u32(&sA[(buf)][a_row[i]][a_c4[i] * 4]),               \
                       a_gp0[i] + kk_, a_sz[i]);                                  \
        _Pragma("unroll")                                                         \
        for (int i = 0; i < 2; i++)                                               \
            cp_async16(smem_u32(&sB[(buf)][b_k[i]][b_c4[i] * 4]),                 \
                       g_w1tf + (size_t)(kk_ + b_k[i]) * HID + block_n +          \
                           b_c4[i] * 4,                                           \
                       16);                                                       \
        cp_commit();                                                              \
    }

    float acc[4][4][4];
#pragma unroll
    for (int mt = 0; mt < 4; mt++)
#pragma unroll
        for (int nt = 0; nt < 4; nt++)
#pragma unroll
            for (int r = 0; r < 4; r++) acc[mt][nt][r] = 0.f;

    G1_ISSUE(0, 0);

    const int NITER = F_IN / 16;         // 8
#pragma unroll
    for (int it = 0; it < NITER; it++) {
        if (it < NITER - 1) {
            G1_ISSUE(it + 1, (it + 1) & 1);
            cp_wait<1>();
        } else {
            cp_wait<0>();
        }
        __syncthreads();
        int p = it & 1;
#pragma unroll
        for (int k8 = 0; k8 < 2; k8++) {
            int kb = k8 * 8;
            unsigned afr[4][4];
#pragma unroll
            for (int mt = 0; mt < 4; mt++) {
                int r = wm * 64 + mt * 16;
                afr[mt][0] = sA[p][r + gq][kb + tg];
                afr[mt][1] = sA[p][r + gq + 8][kb + tg];
                afr[mt][2] = sA[p][r + gq][kb + tg + 4];
                afr[mt][3] = sA[p][r + gq + 8][kb + tg + 4];
            }
            unsigned bfr[4][2];
#pragma unroll
            for (int nt = 0; nt < 4; nt++) {
                int c = wn * 32 + nt * 8 + gq;
                bfr[nt][0] = sB[p][kb + tg][c];
                bfr[nt][1] = sB[p][kb + tg + 4][c];
            }
#pragma unroll
            for (int mt = 0; mt < 4; mt++)
#pragma unroll
                for (int nt = 0; nt < 4; nt++)
                    mma_tf32(acc[mt][nt], afr[mt], bfr[nt]);
        }
        __syncthreads();
    }
#undef G1_ISSUE

    // Epilogue: + bias, BN1 (eval), ReLU, round to tf32 -> g_h1
#pragma unroll
    for (int nt = 0; nt < 4; nt++) {
        int c0 = block_n + wn * 32 + nt * 8 + tg * 2;
        float s0 = __ldg(bg + c0) * rsqrtf(__ldg(bv + c0) + BN_EPS);
        float s1 = __ldg(bg + c0 + 1) * rsqrtf(__ldg(bv + c0 + 1) + BN_EPS);
        float mu0 = __ldg(bm + c0), mu1 = __ldg(bm + c0 + 1);
        float be0 = __ldg(bb + c0), be1 = __ldg(bb + c0 + 1);
        float bi0 = __ldg(b1 + c0), bi1 = __ldg(b1 + c0 + 1);
#pragma unroll
        for (int mt = 0; mt < 4; mt++) {
            int r0 = block_m + wm * 64 + mt * 16 + gq;
#pragma unroll
            for (int h = 0; h < 2; h++) {
                int r = r0 + h * 8;
                if (r < N_NODES) {
                    float v0 = acc[mt][nt][h * 2 + 0] + bi0;
                    float v1 = acc[mt][nt][h * 2 + 1] + bi1;
                    v0 = fmaxf((v0 - mu0) * s0 + be0, 0.f);
                    v1 = fmaxf((v1 - mu1) * s1 + be1, 0.f);
                    g_h1[(size_t)r * HID + c0] = __uint_as_float(tf32r(v0));
                    g_h1[(size_t)r * HID + c0 + 1] = __uint_as_float(tf32r(v1));
                }
            }
        }
    }
}

// ---------------------------------------------------------------------------
// K4: GEMM2 [50000,256]x[256,40] TF32 mma, cp.async 2-stage (R12 proven).
//     CTA 128x40, 8 warps, warp m16 x 5 n8, K chunk 32. Writes g_z only.
// ---------------------------------------------------------------------------
__global__ void __launch_bounds__(256)
gemm2_kernel() {
    __shared__ __align__(16) unsigned sA[2][128][36];
    __shared__ __align__(16) unsigned sB[2][32][44];
    int tid = threadIdx.x;
    int warp = tid >> 5, lane = tid & 31;
    int gq = lane >> 2, tg = lane & 3;
    int block_m = blockIdx.x * 128;

    int a_row[4], a_c4[4], a_sz[4];
    const float* a_gp0[4];
#pragma unroll
    for (int i = 0; i < 4; i++) {
        int f4 = tid + i * 256;
        a_row[i] = f4 >> 3;
        a_c4[i] = f4 & 7;
        int gr = block_m + a_row[i];
        a_sz[i] = (gr < N_NODES) ? 16 : 0;
        a_gp0[i] = g_h1 + (size_t)min(gr, N_NODES - 1) * HID + a_c4[i] * 4;
    }
    int b_k[2], b_c4[2], b_on[2];
#pragma unroll
    for (int i = 0; i < 2; i++) {
        int f4 = tid + i * 256;
        b_on[i] = (f4 < 320);
        int ff = b_on[i] ? f4 : 0;
        b_k[i] = ff / 10;
        b_c4[i] = ff - b_k[i] * 10;
    }

#define G2_ISSUE(chunk, buf)                                                     \
    {                                                                            \
        int kk_ = (chunk) * 32;                                                  \
        _Pragma("unroll")                                                        \
        for (int i = 0; i < 4; i++)                                              \
            cp_async16(smem_u32(&sA[(buf)][a_row[i]][a_c4[i] * 4]),              \
                       a_gp0[i] + kk_, a_sz[i]);                                 \
        _Pragma("unroll")                                                        \
        for (int i = 0; i < 2; i++)                                              \
            if (b_on[i])                                                         \
                cp_async16(smem_u32(&sB[(buf)][b_k[i]][b_c4[i] * 4]),            \
                           g_w2tf + (size_t)(kk_ + b_k[i]) * NCLS + b_c4[i] * 4, \
                           16);                                                  \
        cp_commit();                                                             \
    }

    float acc[5][4];
#pragma unroll
    for (int nt = 0; nt < 5; nt++)
#pragma unroll
        for (int r = 0; r < 4; r++) acc[nt][r] = 0.f;

    G2_ISSUE(0, 0);

    const int NITER = HID / 32;
#pragma unroll
    for (int it = 0; it < NITER; it++) {
        if (it < NITER - 1) {
            G2_ISSUE(it + 1, (it + 1) & 1);
            cp_wait<1>();
        } else {
            cp_wait<0>();
        }
        __syncthreads();
        int p = it & 1;
#pragma unroll
        for (int k8 = 0; k8 < 4; k8++) {
            int kb = k8 * 8;
            unsigned afr[4];
            int r = warp * 16;
            afr[0] = sA[p][r + gq][kb + tg];
            afr[1] = sA[p][r + gq + 8][kb + tg];
            afr[2] = sA[p][r + gq][kb + tg + 4];
            afr[3] = sA[p][r + gq + 8][kb + tg + 4];
#pragma unroll
            for (int nt = 0; nt < 5; nt++) {
                unsigned bfr[2];
                int c = nt * 8 + gq;
                bfr[0] = sB[p][kb + tg][c];
                bfr[1] = sB[p][kb + tg + 4][c];
                mma_tf32(acc[nt], afr, bfr);
            }
        }
        __syncthreads();
    }
#undef G2_ISSUE

#pragma unroll
    for (int nt = 0; nt < 5; nt++) {
        int c0 = nt * 8 + tg * 2;
        int r0 = block_m + warp * 16 + gq;
#pragma unroll
        for (int h = 0; h < 2; h++) {
            int r = r0 + h * 8;
            if (r < N_NODES) {
                g_z[(size_t)r * NCLS + c0] = acc[nt][h * 2 + 0];
                g_z[(size_t)r * NCLS + c0 + 1] = acc[nt][h * 2 + 1];
            }
        }
    }
}

// ---------------------------------------------------------------------------
// K5: gather in logit space + self term + bias. Unrolled x2.
// ---------------------------------------------------------------------------
__global__ void gather40_kernel(const float* __restrict__ b2,
                                float* __restrict__ out) {
    int t = blockIdx.x * blockDim.x + threadIdx.x;
    int node = t / (NCLS / 4);
    if (node >= N_NODES) return;
    int chunk = t - node * (NCLS / 4);
    float4 acc = *(const float4*)(g_z + (size_t)node * NCLS + chunk * 4);
    int beg = g_roff[node];
    int end = (node + 1 < N_NODES) ? g_roff[node + 1] : N_EDGES;
    int j = beg;
    for (; j + 1 < end; j += 2) {
        int s0 = __ldg(g_eidx + j);
        int s1 = __ldg(g_eidx + j + 1);
        float4 v0 = *(const float4*)(g_z + (size_t)s0 * NCLS + chunk * 4);
        float4 v1 = *(const float4*)(g_z + (size_t)s1 * NCLS + chunk * 4);
        acc.x += v0.x; acc.y += v0.y; acc.z += v0.z; acc.w += v0.w;
        acc.x += v1.x; acc.y += v1.y; acc.z += v1.z; acc.w += v1.w;
    }
    if (j < end) {
        int s0 = __ldg(g_eidx + j);
        float4 v0 = *(const float4*)(g_z + (size_t)s0 * NCLS + chunk * 4);
        acc.x += v0.x; acc.y += v0.y; acc.z += v0.z; acc.w += v0.w;
    }
    acc.x += __ldg(b2 + chunk * 4 + 0);
    acc.y += __ldg(b2 + chunk * 4 + 1);
    acc.z += __ldg(b2 + chunk * 4 + 2);
    acc.w += __ldg(b2 + chunk * 4 + 3);
    *(float4*)(out + (size_t)node * NCLS + chunk * 4) = acc;
}

// ---------------------------------------------------------------------------
extern "C" void kernel_launch(void* const* d_in, const int* in_sizes, int n_in,
                              void* d_out, int out_size) {
    const float* x = (const float*)d_in[0];
    const int* ei = (const int*)d_in[1];   // int32 (jax x64-disabled)
    const float* bn0g = (const float*)d_in[2];
    const float* bn0b = (const float*)d_in[3];
    const float* bn0m = (const float*)d_in[4];
    const float* bn0v = (const float*)d_in[5];
    const float* W1 = (const float*)d_in[6];
    const float* b1 = (const float*)d_in[7];
    const float* bn1g = (const float*)d_in[8];
    const float* bn1b = (const float*)d_in[9];
    const float* bn1m = (const float*)d_in[10];
    const float* bn1v = (const float*)d_in[11];
    const float* W2 = (const float*)d_in[12];
    const float* b2 = (const float*)d_in[13];
    float* out = (float*)d_out;

    const int* src = ei;
    const int* dst = ei + N_EDGES;

    // K0: pre-round weights, BN0 affine precompute, zero deg
    convert_w_kernel<<<(N_NODES + 255) / 256, 256>>>(W1, W2, bn0g, bn0b, bn0m, bn0v);
    // CSR build (by dst)
    hist_kernel<<<(N_EDGES + 255) / 256, 256>>>(dst);
    scan_block_kernel<<<N_SCAN_BLOCKS, SCAN_BLK>>>();
    scan_part_kernel<<<1, 64>>>();
    scan_add_kernel<<<(N_NODES + 255) / 256, 256>>>();
    fill_kernel<<<(N_EDGES + 255) / 256, 256>>>(src, dst);
    // K2: gather aggregation fused with BN0 -> g_agg1 (tf32-rounded)
    {
        long long threads = (long long)N_NODES * 32;
        agg128_kernel<<<(int)((threads + 255) / 256), 256>>>((const float4*)x);
    }
    // K3: GEMM1 (tf32 mma, 2-stage cp.async) + BN1 + ReLU -> g_h1
    {
        dim3 grid((N_NODES + 127) / 128, HID / 128);
        gemm1_kernel<<<grid, 256>>>(b1, bn1g, bn1b, bn1m, bn1v);
    }
    // K4: GEMM2 (tf32 mma, 2-stage cp.async) -> g_z
    gemm2_kernel<<<(N_NODES + 127) / 128, 256>>>();
    // K5: gather in logit space + self + bias -> out
    {
        long long threads = (long long)N_NODES * (NCLS / 4);
        gather40_kernel<<<(int)((threads + 255) / 256), 256>>>(b2, out);
    }
}

// round 15
// speedup vs baseline: 1.3059x; 1.3059x over previous
#include <cuda_runtime.h>
#include <math.h>
#include <stdint.h>

#define N_NODES 50000
#define F_IN 128
#define HID 256
#define NCLS 40
#define N_EDGES 600000
#define BN_EPS 1e-5f
#define SCAN_BLK 1024
#define N_SCAN_BLOCKS ((N_NODES + SCAN_BLK - 1) / SCAN_BLK)   // 49

// Scratch (static device globals -- no runtime allocation allowed)
__device__ float g_h0[N_NODES * F_IN];    // BN0(x)  (also: L2 pre-warm for agg)
__device__ float g_agg1[N_NODES * F_IN];  // gather result, tf32-rounded
__device__ float g_h1[N_NODES * HID];     // relu(BN1(...)), tf32-rounded
__device__ float g_z[N_NODES * NCLS];     // h1 @ W2 (pre-aggregation logits)
__device__ float g_w1tf[F_IN * HID];      // W1 pre-rounded to tf32
__device__ float g_w2tf[HID * NCLS];      // W2 pre-rounded to tf32
// CSR-by-dst scratch
__device__ int g_deg[N_NODES];
__device__ int g_roff[N_NODES];           // exclusive offsets
__device__ int g_cur[N_NODES];            // fill cursors
__device__ int g_part[64];                // per-block scan partials
__device__ int g_eidx[N_EDGES];           // src ids grouped by dst

__device__ __forceinline__ int clamp_idx(int i) {
    i = i < 0 ? 0 : i;
    return i >= N_NODES ? N_NODES - 1 : i;
}

// Round-to-nearest f32 -> tf32 (kept in 32-bit container)
__device__ __forceinline__ unsigned tf32r(float x) {
    unsigned r;
    asm("cvt.rna.tf32.f32 %0, %1;" : "=r"(r) : "f"(x));
    return r;
}

// D += A*B for one m16n8k8 tf32 tile
__device__ __forceinline__ void mma_tf32(float* d, const unsigned* a, const unsigned* b) {
    asm volatile(
        "mma.sync.aligned.m16n8k8.row.col.f32.tf32.tf32.f32 "
        "{%0,%1,%2,%3}, {%4,%5,%6,%7}, {%8,%9}, {%0,%1,%2,%3};"
        : "+f"(d[0]), "+f"(d[1]), "+f"(d[2]), "+f"(d[3])
        : "r"(a[0]), "r"(a[1]), "r"(a[2]), "r"(a[3]), "r"(b[0]), "r"(b[1]));
}

__device__ __forceinline__ void cp_async16(uint32_t saddr, const void* gptr, int sz) {
    asm volatile("cp.async.cg.shared.global [%0], [%1], 16, %2;"
                 :: "r"(saddr), "l"(gptr), "r"(sz) : "memory");
}
__device__ __forceinline__ void cp_commit() {
    asm volatile("cp.async.commit_group;" ::: "memory");
}
template <int N>
__device__ __forceinline__ void cp_wait() {
    asm volatile("cp.async.wait_group %0;" :: "n"(N) : "memory");
}
__device__ __forceinline__ uint32_t smem_u32(const void* p) {
    return (uint32_t)__cvta_generic_to_shared(p);
}

// ---------------------------------------------------------------------------
// K0: weight pre-rounding to tf32 + deg zeroing
// ---------------------------------------------------------------------------
__global__ void convert_w_kernel(const float* __restrict__ W1,
                                 const float* __restrict__ W2) {
    int i = blockIdx.x * blockDim.x + threadIdx.x;
    if (i < F_IN * HID) g_w1tf[i] = __uint_as_float(tf32r(W1[i]));
    if (i < HID * NCLS) g_w2tf[i] = __uint_as_float(tf32r(W2[i]));
    if (i < N_NODES) g_deg[i] = 0;
}

// ---------------------------------------------------------------------------
// K1: BN0 over input features -> g_h0  (also L2-warms the gather source)
// ---------------------------------------------------------------------------
__global__ void bn0_kernel(const float4* __restrict__ x,
                           const float* __restrict__ g, const float* __restrict__ b,
                           const float* __restrict__ m, const float* __restrict__ v) {
    int idx = blockIdx.x * blockDim.x + threadIdx.x;
    const int total = N_NODES * (F_IN / 4);
    if (idx >= total) return;
    int c = (idx & (F_IN / 4 - 1)) * 4;
    float4 xv = x[idx];
    float4 o;
    o.x = (xv.x - __ldg(m + c + 0)) * (__ldg(g + c + 0) * rsqrtf(__ldg(v + c + 0) + BN_EPS)) + __ldg(b + c + 0);
    o.y = (xv.y - __ldg(m + c + 1)) * (__ldg(g + c + 1) * rsqrtf(__ldg(v + c + 1) + BN_EPS)) + __ldg(b + c + 1);
    o.z = (xv.z - __ldg(m + c + 2)) * (__ldg(g + c + 2) * rsqrtf(__ldg(v + c + 2) + BN_EPS)) + __ldg(b + c + 2);
    o.w = (xv.w - __ldg(m + c + 3)) * (__ldg(g + c + 3) * rsqrtf(__ldg(v + c + 3) + BN_EPS)) + __ldg(b + c + 3);
    ((float4*)g_h0)[idx] = o;
}

// ---------------------------------------------------------------------------
// CSR build: hist -> block scan -> add (inline partial sum) -> fill
// ---------------------------------------------------------------------------
__global__ void hist_kernel(const int* __restrict__ dst) {
    int e = blockIdx.x * blockDim.x + threadIdx.x;
    if (e >= N_EDGES) return;
    atomicAdd(&g_deg[clamp_idx(__ldg(dst + e))], 1);
}

__global__ void scan_block_kernel() {
    __shared__ int wsum[32];
    int tid = threadIdx.x;
    int i = blockIdx.x * SCAN_BLK + tid;
    int lane = tid & 31, wid = tid >> 5;
    int v = (i < N_NODES) ? g_deg[i] : 0;
    int s = v;
#pragma unroll
    for (int off = 1; off < 32; off <<= 1) {
        int u = __shfl_up_sync(0xFFFFFFFFu, s, off);
        if (lane >= off) s += u;
    }
    if (lane == 31) wsum[wid] = s;
    __syncthreads();
    if (wid == 0) {
        int ws = wsum[lane];
        int t = ws;
#pragma unroll
        for (int off = 1; off < 32; off <<= 1) {
            int u = __shfl_up_sync(0xFFFFFFFFu, t, off);
            if (lane >= off) t += u;
        }
        wsum[lane] = t - ws;                  // exclusive warp prefix
        if (lane == 31) g_part[blockIdx.x] = t;  // block total
    }
    __syncthreads();
    if (i < N_NODES) g_roff[i] = s - v + wsum[wid];
}

// scan_add with inline partial-prefix (replaces separate scan_part kernel):
// each thread sums block totals before its block (<=48 uniform cached loads).
__global__ void scan_add_kernel() {
    int i = blockIdx.x * blockDim.x + threadIdx.x;
    if (i >= N_NODES) return;
    int nb = i / SCAN_BLK;
    int add = 0;
    for (int b = 0; b < nb; b++) add += __ldg(g_part + b);
    int r = g_roff[i] + add;
    g_roff[i] = r;
    g_cur[i] = r;
}

__global__ void fill_kernel(const int* __restrict__ src, const int* __restrict__ dst) {
    int e = blockIdx.x * blockDim.x + threadIdx.x;
    if (e >= N_EDGES) return;
    int d = clamp_idx(__ldg(dst + e));
    int s = clamp_idx(__ldg(src + e));
    int p = atomicAdd(&g_cur[d], 1);
    g_eidx[p] = s;
}

// ---------------------------------------------------------------------------
// K2: gather aggregation, F=128. One warp per node; lane owns one float4.
//     agg1[i] = h0[i] + sum_{j in N(i)} h0[j], written tf32-rounded.
// ---------------------------------------------------------------------------
__global__ void agg128_kernel() {
    int node = (blockIdx.x * blockDim.x + threadIdx.x) >> 5;
    if (node >= N_NODES) return;
    int lane = threadIdx.x & 31;
    float4 acc = ((const float4*)(g_h0 + (size_t)node * F_IN))[lane];
    int beg = g_roff[node];
    int end = (node + 1 < N_NODES) ? g_roff[node + 1] : N_EDGES;
    int j = beg;
    for (; j + 1 < end; j += 2) {
        int s0 = __ldg(g_eidx + j);
        int s1 = __ldg(g_eidx + j + 1);
        float4 v0 = ((const float4*)(g_h0 + (size_t)s0 * F_IN))[lane];
        float4 v1 = ((const float4*)(g_h0 + (size_t)s1 * F_IN))[lane];
        acc.x += v0.x; acc.y += v0.y; acc.z += v0.z; acc.w += v0.w;
        acc.x += v1.x; acc.y += v1.y; acc.z += v1.z; acc.w += v1.w;
    }
    if (j < end) {
        int s0 = __ldg(g_eidx + j);
        float4 v0 = ((const float4*)(g_h0 + (size_t)s0 * F_IN))[lane];
        acc.x += v0.x; acc.y += v0.y; acc.z += v0.z; acc.w += v0.w;
    }
    float4 o;
    o.x = __uint_as_float(tf32r(acc.x));
    o.y = __uint_as_float(tf32r(acc.y));
    o.z = __uint_as_float(tf32r(acc.z));
    o.w = __uint_as_float(tf32r(acc.w));
    ((float4*)(g_agg1 + (size_t)node * F_IN))[lane] = o;
}

// ---------------------------------------------------------------------------
// K3: GEMM1 [50000,128]x[128,256] + bias + BN1 + ReLU -> g_h1 (tf32-rounded).
//     TF32 mma, cp.async 2-stage pipeline (R12 proven). CTA 128x128, BK=16.
// ---------------------------------------------------------------------------
__global__ void __launch_bounds__(256)
gemm1_kernel(const float* __restrict__ b1,
             const float* __restrict__ bg, const float* __restrict__ bb,
             const float* __restrict__ bm, const float* __restrict__ bv) {
    __shared__ __align__(16) unsigned sA[2][128][20];   // [buf][m][k]
    __shared__ __align__(16) unsigned sB[2][16][136];   // [buf][k][n]
    int tid = threadIdx.x;
    int warp = tid >> 5, lane = tid & 31;
    int wm = warp >> 2, wn = warp & 3;
    int gq = lane >> 2, tg = lane & 3;
    int block_m = blockIdx.x * 128;
    int block_n = blockIdx.y * 128;

    int a_row[2], a_c4[2], a_sz[2];
    const float* a_gp0[2];
#pragma unroll
    for (int i = 0; i < 2; i++) {
        int f4 = tid + i * 256;          // 0..511
        a_row[i] = f4 >> 2;              // 0..127
        a_c4[i] = f4 & 3;                // 0..3
        int gr = block_m + a_row[i];
        a_sz[i] = (gr < N_NODES) ? 16 : 0;
        a_gp0[i] = g_agg1 + (size_t)min(gr, N_NODES - 1) * F_IN + a_c4[i] * 4;
    }
    int b_k[2], b_c4[2];
#pragma unroll
    for (int i = 0; i < 2; i++) {
        int f4 = tid + i * 256;
        b_k[i] = f4 >> 5;                // 0..15
        b_c4[i] = f4 & 31;               // 0..31
    }

#define G1_ISSUE(chunk, buf)                                                      \
    {                                                                             \
        int kk_ = (chunk) * 16;                                                   \
        _Pragma("unroll")                                                         \
        for (int i = 0; i < 2; i++)                                               \
            cp_async16(smem_u32(&sA[(buf)][a_row[i]][a_c4[i] * 4]),               \
                       a_gp0[i] + kk_, a_sz[i]);                                  \
        _Pragma("unroll")                                                         \
        for (int i = 0; i < 2; i++)                                               \
            cp_async16(smem_u32(&sB[(buf)][b_k[i]][b_c4[i] * 4]),                 \
                       g_w1tf + (size_t)(kk_ + b_k[i]) * HID + block_n +          \
                           b_c4[i] * 4,                                           \
                       16);                                                       \
        cp_commit();                                                              \
    }

    float acc[4][4][4];
#pragma unroll
    for (int mt = 0; mt < 4; mt++)
#pragma unroll
        for (int nt = 0; nt < 4; nt++)
#pragma unroll
            for (int r = 0; r < 4; r++) acc[mt][nt][r] = 0.f;

    G1_ISSUE(0, 0);

    const int NITER = F_IN / 16;         // 8
#pragma unroll
    for (int it = 0; it < NITER; it++) {
        if (it < NITER - 1) {
            G1_ISSUE(it + 1, (it + 1) & 1);
            cp_wait<1>();
        } else {
            cp_wait<0>();
        }
        __syncthreads();
        int p = it & 1;
#pragma unroll
        for (int k8 = 0; k8 < 2; k8++) {
            int kb = k8 * 8;
            unsigned afr[4][4];
#pragma unroll
            for (int mt = 0; mt < 4; mt++) {
                int r = wm * 64 + mt * 16;
                afr[mt][0] = sA[p][r + gq][kb + tg];
                afr[mt][1] = sA[p][r + gq + 8][kb + tg];
                afr[mt][2] = sA[p][r + gq][kb + tg + 4];
                afr[mt][3] = sA[p][r + gq + 8][kb + tg + 4];
            }
            unsigned bfr[4][2];
#pragma unroll
            for (int nt = 0; nt < 4; nt++) {
                int c = wn * 32 + nt * 8 + gq;
                bfr[nt][0] = sB[p][kb + tg][c];
                bfr[nt][1] = sB[p][kb + tg + 4][c];
            }
#pragma unroll
            for (int mt = 0; mt < 4; mt++)
#pragma unroll
                for (int nt = 0; nt < 4; nt++)
                    mma_tf32(acc[mt][nt], afr[mt], bfr[nt]);
        }
        __syncthreads();
    }
#undef G1_ISSUE

    // Epilogue: + bias, BN1 (eval), ReLU, round to tf32 -> g_h1
#pragma unroll
    for (int nt = 0; nt < 4; nt++) {
        int c0 = block_n + wn * 32 + nt * 8 + tg * 2;
        float s0 = __ldg(bg + c0) * rsqrtf(__ldg(bv + c0) + BN_EPS);
        float s1 = __ldg(bg + c0 + 1) * rsqrtf(__ldg(bv + c0 + 1) + BN_EPS);
        float mu0 = __ldg(bm + c0), mu1 = __ldg(bm + c0 + 1);
        float be0 = __ldg(bb + c0), be1 = __ldg(bb + c0 + 1);
        float bi0 = __ldg(b1 + c0), bi1 = __ldg(b1 + c0 + 1);
#pragma unroll
        for (int mt = 0; mt < 4; mt++) {
            int r0 = block_m + wm * 64 + mt * 16 + gq;
#pragma unroll
            for (int h = 0; h < 2; h++) {
                int r = r0 + h * 8;
                if (r < N_NODES) {
                    float v0 = acc[mt][nt][h * 2 + 0] + bi0;
                    float v1 = acc[mt][nt][h * 2 + 1] + bi1;
                    v0 = fmaxf((v0 - mu0) * s0 + be0, 0.f);
                    v1 = fmaxf((v1 - mu1) * s1 + be1, 0.f);
                    g_h1[(size_t)r * HID + c0] = __uint_as_float(tf32r(v0));
                    g_h1[(size_t)r * HID + c0 + 1] = __uint_as_float(tf32r(v1));
                }
            }
        }
    }
}

// ---------------------------------------------------------------------------
// K4: GEMM2 [50000,256]x[256,40] TF32 mma, cp.async 2-stage (R12 proven).
//     CTA 128x40, 8 warps, warp m16 x 5 n8, K chunk 32. Writes g_z only.
// ---------------------------------------------------------------------------
__global__ void __launch_bounds__(256)
gemm2_kernel() {
    __shared__ __align__(16) unsigned sA[2][128][36];
    __shared__ __align__(16) unsigned sB[2][32][44];
    int tid = threadIdx.x;
    int warp = tid >> 5, lane = tid & 31;
    int gq = lane >> 2, tg = lane & 3;
    int block_m = blockIdx.x * 128;

    int a_row[4], a_c4[4], a_sz[4];
    const float* a_gp0[4];
#pragma unroll
    for (int i = 0; i < 4; i++) {
        int f4 = tid + i * 256;
        a_row[i] = f4 >> 3;
        a_c4[i] = f4 & 7;
        int gr = block_m + a_row[i];
        a_sz[i] = (gr < N_NODES) ? 16 : 0;
        a_gp0[i] = g_h1 + (size_t)min(gr, N_NODES - 1) * HID + a_c4[i] * 4;
    }
    int b_k[2], b_c4[2], b_on[2];
#pragma unroll
    for (int i = 0; i < 2; i++) {
        int f4 = tid + i * 256;
        b_on[i] = (f4 < 320);
        int ff = b_on[i] ? f4 : 0;
        b_k[i] = ff / 10;
        b_c4[i] = ff - b_k[i] * 10;
    }

#define G2_ISSUE(chunk, buf)                                                     \
    {                                                                            \
        int kk_ = (chunk) * 32;                                                  \
        _Pragma("unroll")                                                        \
        for (int i = 0; i < 4; i++)                                              \
            cp_async16(smem_u32(&sA[(buf)][a_row[i]][a_c4[i] * 4]),              \
                       a_gp0[i] + kk_, a_sz[i]);                                 \
        _Pragma("unroll")                                                        \
        for (int i = 0; i < 2; i++)                                              \
            if (b_on[i])                                                         \
                cp_async16(smem_u32(&sB[(buf)][b_k[i]][b_c4[i] * 4]),            \
                           g_w2tf + (size_t)(kk_ + b_k[i]) * NCLS + b_c4[i] * 4, \
                           16);                                                  \
        cp_commit();                                                             \
    }

    float acc[5][4];
#pragma unroll
    for (int nt = 0; nt < 5; nt++)
#pragma unroll
        for (int r = 0; r < 4; r++) acc[nt][r] = 0.f;

    G2_ISSUE(0, 0);

    const int NITER = HID / 32;
#pragma unroll
    for (int it = 0; it < NITER; it++) {
        if (it < NITER - 1) {
            G2_ISSUE(it + 1, (it + 1) & 1);
            cp_wait<1>();
        } else {
            cp_wait<0>();
        }
        __syncthreads();
        int p = it & 1;
#pragma unroll
        for (int k8 = 0; k8 < 4; k8++) {
            int kb = k8 * 8;
            unsigned afr[4];
            int r = warp * 16;
            afr[0] = sA[p][r + gq][kb + tg];
            afr[1] = sA[p][r + gq + 8][kb + tg];
            afr[2] = sA[p][r + gq][kb + tg + 4];
            afr[3] = sA[p][r + gq + 8][kb + tg + 4];
#pragma unroll
            for (int nt = 0; nt < 5; nt++) {
                unsigned bfr[2];
                int c = nt * 8 + gq;
                bfr[0] = sB[p][kb + tg][c];
                bfr[1] = sB[p][kb + tg + 4][c];
                mma_tf32(acc[nt], afr, bfr);
            }
        }
        __syncthreads();
    }
#undef G2_ISSUE

#pragma unroll
    for (int nt = 0; nt < 5; nt++) {
        int c0 = nt * 8 + tg * 2;
        int r0 = block_m + warp * 16 + gq;
#pragma unroll
        for (int h = 0; h < 2; h++) {
            int r = r0 + h * 8;
            if (r < N_NODES) {
                g_z[(size_t)r * NCLS + c0] = acc[nt][h * 2 + 0];
                g_z[(size_t)r * NCLS + c0 + 1] = acc[nt][h * 2 + 1];
            }
        }
    }
}

// ---------------------------------------------------------------------------
// K5: gather in logit space + self term + bias. Unrolled x2.
// ---------------------------------------------------------------------------
__global__ void gather40_kernel(const float* __restrict__ b2,
                                float* __restrict__ out) {
    int t = blockIdx.x * blockDim.x + threadIdx.x;
    int node = t / (NCLS / 4);
    if (node >= N_NODES) return;
    int chunk = t - node * (NCLS / 4);
    float4 acc = *(const float4*)(g_z + (size_t)node * NCLS + chunk * 4);
    int beg = g_roff[node];
    int end = (node + 1 < N_NODES) ? g_roff[node + 1] : N_EDGES;
    int j = beg;
    for (; j + 1 < end; j += 2) {
        int s0 = __ldg(g_eidx + j);
        int s1 = __ldg(g_eidx + j + 1);
        float4 v0 = *(const float4*)(g_z + (size_t)s0 * NCLS + chunk * 4);
        float4 v1 = *(const float4*)(g_z + (size_t)s1 * NCLS + chunk * 4);
        acc.x += v0.x; acc.y += v0.y; acc.z += v0.z; acc.w += v0.w;
        acc.x += v1.x; acc.y += v1.y; acc.z += v1.z; acc.w += v1.w;
    }
    if (j < end) {
        int s0 = __ldg(g_eidx + j);
        float4 v0 = *(const float4*)(g_z + (size_t)s0 * NCLS + chunk * 4);
        acc.x += v0.x; acc.y += v0.y; acc.z += v0.z; acc.w += v0.w;
    }
    acc.x += __ldg(b2 + chunk * 4 + 0);
    acc.y += __ldg(b2 + chunk * 4 + 1);
    acc.z += __ldg(b2 + chunk * 4 + 2);
    acc.w += __ldg(b2 + chunk * 4 + 3);
    *(float4*)(out + (size_t)node * NCLS + chunk * 4) = acc;
}

// ---------------------------------------------------------------------------
extern "C" void kernel_launch(void* const* d_in, const int* in_sizes, int n_in,
                              void* d_out, int out_size) {
    const float* x = (const float*)d_in[0];
    const int* ei = (const int*)d_in[1];   // int32 (jax x64-disabled)
    const float* bn0g = (const float*)d_in[2];
    const float* bn0b = (const float*)d_in[3];
    const float* bn0m = (const float*)d_in[4];
    const float* bn0v = (const float*)d_in[5];
    const float* W1 = (const float*)d_in[6];
    const float* b1 = (const float*)d_in[7];
    const float* bn1g = (const float*)d_in[8];
    const float* bn1b = (const float*)d_in[9];
    const float* bn1m = (const float*)d_in[10];
    const float* bn1v = (const float*)d_in[11];
    const float* W2 = (const float*)d_in[12];
    const float* b2 = (const float*)d_in[13];
    float* out = (float*)d_out;

    const int* src = ei;
    const int* dst = ei + N_EDGES;

    // K0: pre-round weights + zero deg
    convert_w_kernel<<<(N_NODES + 255) / 256, 256>>>(W1, W2);
    // K1: BN0 -> g_h0 (re-warms L2 for the gather each replay)
    {
        int total = N_NODES * (F_IN / 4);
        bn0_kernel<<<(total + 255) / 256, 256>>>((const float4*)x, bn0g, bn0b, bn0m, bn0v);
    }
    // CSR build (by dst)
    hist_kernel<<<(N_EDGES + 255) / 256, 256>>>(dst);
    scan_block_kernel<<<N_SCAN_BLOCKS, SCAN_BLK>>>();
    scan_add_kernel<<<(N_NODES + 255) / 256, 256>>>();
    fill_kernel<<<(N_EDGES + 255) / 256, 256>>>(src, dst);
    // K2: gather aggregation (F=128) -> g_agg1 (tf32-rounded)
    {
        long long threads = (long long)N_NODES * 32;
        agg128_kernel<<<(int)((threads + 255) / 256), 256>>>();
    }
    // K3: GEMM1 (tf32 mma, 2-stage cp.async) + BN1 + ReLU -> g_h1
    {
        dim3 grid((N_NODES + 127) / 128, HID / 128);
        gemm1_kernel<<<grid, 256>>>(b1, bn1g, bn1b, bn1m, bn1v);
    }
    // K4: GEMM2 (tf32 mma, 2-stage cp.async) -> g_z
    gemm2_kernel<<<(N_NODES + 127) / 128, 256>>>();
    // K5: gather in logit space + self + bias -> out
    {
        long long threads = (long long)N_NODES * (NCLS / 4);
        gather40_kernel<<<(int)((threads + 255) / 256), 256>>>(b2, out);
    }
}

// round 16
// speedup vs baseline: 1.3281x; 1.0170x over previous
#include <cuda_runtime.h>
#include <math.h>
#include <stdint.h>

#define N_NODES 50000
#define F_IN 128
#define HID 256
#define NCLS 40
#define N_EDGES 600000
#define BN_EPS 1e-5f
#define SCAN_BLK 1024
#define N_SCAN_BLOCKS ((N_NODES + SCAN_BLK - 1) / SCAN_BLK)   // 49

// Scratch (static device globals -- no runtime allocation allowed)
__device__ float g_h0[N_NODES * F_IN];    // BN0(x)  (also: L2 pre-warm for agg)
__device__ float g_agg1[N_NODES * F_IN];  // gather result, tf32-rounded
__device__ float g_h1[N_NODES * HID];     // relu(BN1(...)), tf32-rounded
__device__ float g_z[N_NODES * NCLS];     // h1 @ W2 (pre-aggregation logits)
__device__ float g_w1tf[F_IN * HID];      // W1 pre-rounded to tf32
__device__ float g_w2tf[HID * NCLS];      // W2 pre-rounded to tf32
// CSR-by-dst scratch
__device__ int g_deg[N_NODES];
__device__ int g_roff[N_NODES];           // exclusive offsets
__device__ int g_cur[N_NODES];            // fill cursors
__device__ int g_part[64];                // per-block scan partials
__device__ int g_eidx[N_EDGES];           // src ids grouped by dst

__device__ __forceinline__ int clamp_idx(int i) {
    i = i < 0 ? 0 : i;
    return i >= N_NODES ? N_NODES - 1 : i;
}

// Round-to-nearest f32 -> tf32 (kept in 32-bit container)
__device__ __forceinline__ unsigned tf32r(float x) {
    unsigned r;
    asm("cvt.rna.tf32.f32 %0, %1;" : "=r"(r) : "f"(x));
    return r;
}

// D += A*B for one m16n8k8 tf32 tile
__device__ __forceinline__ void mma_tf32(float* d, const unsigned* a, const unsigned* b) {
    asm volatile(
        "mma.sync.aligned.m16n8k8.row.col.f32.tf32.tf32.f32 "
        "{%0,%1,%2,%3}, {%4,%5,%6,%7}, {%8,%9}, {%0,%1,%2,%3};"
        : "+f"(d[0]), "+f"(d[1]), "+f"(d[2]), "+f"(d[3])
        : "r"(a[0]), "r"(a[1]), "r"(a[2]), "r"(a[3]), "r"(b[0]), "r"(b[1]));
}

__device__ __forceinline__ void cp_async16(uint32_t saddr, const void* gptr, int sz) {
    asm volatile("cp.async.cg.shared.global [%0], [%1], 16, %2;"
                 :: "r"(saddr), "l"(gptr), "r"(sz) : "memory");
}
__device__ __forceinline__ void cp_commit() {
    asm volatile("cp.async.commit_group;" ::: "memory");
}
template <int N>
__device__ __forceinline__ void cp_wait() {
    asm volatile("cp.async.wait_group %0;" :: "n"(N) : "memory");
}
__device__ __forceinline__ uint32_t smem_u32(const void* p) {
    return (uint32_t)__cvta_generic_to_shared(p);
}

// ---------------------------------------------------------------------------
// K0: weight pre-rounding to tf32 + deg zeroing
// ---------------------------------------------------------------------------
__global__ void convert_w_kernel(const float* __restrict__ W1,
                                 const float* __restrict__ W2) {
    int i = blockIdx.x * blockDim.x + threadIdx.x;
    if (i < F_IN * HID) g_w1tf[i] = __uint_as_float(tf32r(W1[i]));
    if (i < HID * NCLS) g_w2tf[i] = __uint_as_float(tf32r(W2[i]));
    if (i < N_NODES) g_deg[i] = 0;
}

// ---------------------------------------------------------------------------
// K1: FUSED bn0 + hist. Independent work items packed into one launch:
//     - every thread: one float4 of BN0(x) -> g_h0 (also L2-warms gather src)
//     - first N_EDGES threads: one degree-histogram atomic
// ---------------------------------------------------------------------------
__global__ void bn0_hist_kernel(const float4* __restrict__ x,
                                const float* __restrict__ g, const float* __restrict__ b,
                                const float* __restrict__ m, const float* __restrict__ v,
                                const int* __restrict__ dst) {
    int idx = blockIdx.x * blockDim.x + threadIdx.x;
    const int total = N_NODES * (F_IN / 4);      // 1.6M
    if (idx < N_EDGES)
        atomicAdd(&g_deg[clamp_idx(__ldg(dst + idx))], 1);
    if (idx >= total) return;
    int c = (idx & (F_IN / 4 - 1)) * 4;
    float4 xv = x[idx];
    float4 o;
    o.x = (xv.x - __ldg(m + c + 0)) * (__ldg(g + c + 0) * rsqrtf(__ldg(v + c + 0) + BN_EPS)) + __ldg(b + c + 0);
    o.y = (xv.y - __ldg(m + c + 1)) * (__ldg(g + c + 1) * rsqrtf(__ldg(v + c + 1) + BN_EPS)) + __ldg(b + c + 1);
    o.z = (xv.z - __ldg(m + c + 2)) * (__ldg(g + c + 2) * rsqrtf(__ldg(v + c + 2) + BN_EPS)) + __ldg(b + c + 2);
    o.w = (xv.w - __ldg(m + c + 3)) * (__ldg(g + c + 3) * rsqrtf(__ldg(v + c + 3) + BN_EPS)) + __ldg(b + c + 3);
    ((float4*)g_h0)[idx] = o;
}

// ---------------------------------------------------------------------------
// CSR build (cont.): block scan -> add (inline partial sum) -> fill
// ---------------------------------------------------------------------------
__global__ void scan_block_kernel() {
    __shared__ int wsum[32];
    int tid = threadIdx.x;
    int i = blockIdx.x * SCAN_BLK + tid;
    int lane = tid & 31, wid = tid >> 5;
    int v = (i < N_NODES) ? g_deg[i] : 0;
    int s = v;
#pragma unroll
    for (int off = 1; off < 32; off <<= 1) {
        int u = __shfl_up_sync(0xFFFFFFFFu, s, off);
        if (lane >= off) s += u;
    }
    if (lane == 31) wsum[wid] = s;
    __syncthreads();
    if (wid == 0) {
        int ws = wsum[lane];
        int t = ws;
#pragma unroll
        for (int off = 1; off < 32; off <<= 1) {
            int u = __shfl_up_sync(0xFFFFFFFFu, t, off);
            if (lane >= off) t += u;
        }
        wsum[lane] = t - ws;                  // exclusive warp prefix
        if (lane == 31) g_part[blockIdx.x] = t;  // block total
    }
    __syncthreads();
    if (i < N_NODES) g_roff[i] = s - v + wsum[wid];
}

// scan_add with inline partial-prefix: each thread sums block totals before
// its block (<=48 uniform cached loads).
__global__ void scan_add_kernel() {
    int i = blockIdx.x * blockDim.x + threadIdx.x;
    if (i >= N_NODES) return;
    int nb = i / SCAN_BLK;
    int add = 0;
    for (int b = 0; b < nb; b++) add += __ldg(g_part + b);
    int r = g_roff[i] + add;
    g_roff[i] = r;
    g_cur[i] = r;
}

__global__ void fill_kernel(const int* __restrict__ src, const int* __restrict__ dst) {
    int e = blockIdx.x * blockDim.x + threadIdx.x;
    if (e >= N_EDGES) return;
    int d = clamp_idx(__ldg(dst + e));
    int s = clamp_idx(__ldg(src + e));
    int p = atomicAdd(&g_cur[d], 1);
    g_eidx[p] = s;
}

// ---------------------------------------------------------------------------
// K2: gather aggregation, F=128. One warp per node; lane owns one float4.
//     agg1[i] = h0[i] + sum_{j in N(i)} h0[j], written tf32-rounded.
// ---------------------------------------------------------------------------
__global__ void agg128_kernel() {
    int node = (blockIdx.x * blockDim.x + threadIdx.x) >> 5;
    if (node >= N_NODES) return;
    int lane = threadIdx.x & 31;
    float4 acc = ((const float4*)(g_h0 + (size_t)node * F_IN))[lane];
    int beg = g_roff[node];
    int end = (node + 1 < N_NODES) ? g_roff[node + 1] : N_EDGES;
    int j = beg;
    for (; j + 1 < end; j += 2) {
        int s0 = __ldg(g_eidx + j);
        int s1 = __ldg(g_eidx + j + 1);
        float4 v0 = ((const float4*)(g_h0 + (size_t)s0 * F_IN))[lane];
        float4 v1 = ((const float4*)(g_h0 + (size_t)s1 * F_IN))[lane];
        acc.x += v0.x; acc.y += v0.y; acc.z += v0.z; acc.w += v0.w;
        acc.x += v1.x; acc.y += v1.y; acc.z += v1.z; acc.w += v1.w;
    }
    if (j < end) {
        int s0 = __ldg(g_eidx + j);
        float4 v0 = ((const float4*)(g_h0 + (size_t)s0 * F_IN))[lane];
        acc.x += v0.x; acc.y += v0.y; acc.z += v0.z; acc.w += v0.w;
    }
    float4 o;
    o.x = __uint_as_float(tf32r(acc.x));
    o.y = __uint_as_float(tf32r(acc.y));
    o.z = __uint_as_float(tf32r(acc.z));
    o.w = __uint_as_float(tf32r(acc.w));
    ((float4*)(g_agg1 + (size_t)node * F_IN))[lane] = o;
}

// ---------------------------------------------------------------------------
// K3: GEMM1 [50000,128]x[128,256] + bias + BN1 + ReLU -> g_h1 (tf32-rounded).
//     TF32 mma, cp.async 2-stage pipeline (R12 proven). CTA 128x128, BK=16.
// ---------------------------------------------------------------------------
__global__ void __launch_bounds__(256)
gemm1_kernel(const float* __restrict__ b1,
             const float* __restrict__ bg, const float* __restrict__ bb,
             const float* __restrict__ bm, const float* __restrict__ bv) {
    __shared__ __align__(16) unsigned sA[2][128][20];   // [buf][m][k]
    __shared__ __align__(16) unsigned sB[2][16][136];   // [buf][k][n]
    int tid = threadIdx.x;
    int warp = tid >> 5, lane = tid & 31;
    int wm = warp >> 2, wn = warp & 3;
    int gq = lane >> 2, tg = lane & 3;
    int block_m = blockIdx.x * 128;
    int block_n = blockIdx.y * 128;

    int a_row[2], a_c4[2], a_sz[2];
    const float* a_gp0[2];
#pragma unroll
    for (int i = 0; i < 2; i++) {
        int f4 = tid + i * 256;          // 0..511
        a_row[i] = f4 >> 2;              // 0..127
        a_c4[i] = f4 & 3;                // 0..3
        int gr = block_m + a_row[i];
        a_sz[i] = (gr < N_NODES) ? 16 : 0;
        a_gp0[i] = g_agg1 + (size_t)min(gr, N_NODES - 1) * F_IN + a_c4[i] * 4;
    }
    int b_k[2], b_c4[2];
#pragma unroll
    for (int i = 0; i < 2; i++) {
        int f4 = tid + i * 256;
        b_k[i] = f4 >> 5;                // 0..15
        b_c4[i] = f4 & 31;               // 0..31
    }

#define G1_ISSUE(chunk, buf)                                                      \
    {                                                                             \
        int kk_ = (chunk) * 16;                                                   \
        _Pragma("unroll")                                                         \
        for (int i = 0; i < 2; i++)                                               \
            cp_async16(smem_u32(&sA[(buf)][a_row[i]][a_c4[i] * 4]),               \
                       a_gp0[i] + kk_, a_sz[i]);                                  \
        _Pragma("unroll")                                                         \
        for (int i = 0; i < 2; i++)                                               \
            cp_async16(smem_u32(&sB[(buf)][b_k[i]][b_c4[i] * 4]),                 \
                       g_w1tf + (size_t)(kk_ + b_k[i]) * HID + block_n +          \
                           b_c4[i] * 4,                                           \
                       16);                                                       \
        cp_commit();                                                              \
    }

    float acc[4][4][4];
#pragma unroll
    for (int mt = 0; mt < 4; mt++)
#pragma unroll
        for (int nt = 0; nt < 4; nt++)
#pragma unroll
            for (int r = 0; r < 4; r++) acc[mt][nt][r] = 0.f;

    G1_ISSUE(0, 0);

    const int NITER = F_IN / 16;         // 8
#pragma unroll
    for (int it = 0; it < NITER; it++) {
        if (it < NITER - 1) {
            G1_ISSUE(it + 1, (it + 1) & 1);
            cp_wait<1>();
        } else {
            cp_wait<0>();
        }
        __syncthreads();
        int p = it & 1;
#pragma unroll
        for (int k8 = 0; k8 < 2; k8++) {
            int kb = k8 * 8;
            unsigned afr[4][4];
#pragma unroll
            for (int mt = 0; mt < 4; mt++) {
                int r = wm * 64 + mt * 16;
                afr[mt][0] = sA[p][r + gq][kb + tg];
                afr[mt][1] = sA[p][r + gq + 8][kb + tg];
                afr[mt][2] = sA[p][r + gq][kb + tg + 4];
                afr[mt][3] = sA[p][r + gq + 8][kb + tg + 4];
            }
            unsigned bfr[4][2];
#pragma unroll
            for (int nt = 0; nt < 4; nt++) {
                int c = wn * 32 + nt * 8 + gq;
                bfr[nt][0] = sB[p][kb + tg][c];
                bfr[nt][1] = sB[p][kb + tg + 4][c];
            }
#pragma unroll
            for (int mt = 0; mt < 4; mt++)
#pragma unroll
                for (int nt = 0; nt < 4; nt++)
                    mma_tf32(acc[mt][nt], afr[mt], bfr[nt]);
        }
        __syncthreads();
    }
#undef G1_ISSUE

    // Epilogue: + bias, BN1 (eval), ReLU, round to tf32 -> g_h1
#pragma unroll
    for (int nt = 0; nt < 4; nt++) {
        int c0 = block_n + wn * 32 + nt * 8 + tg * 2;
        float s0 = __ldg(bg + c0) * rsqrtf(__ldg(bv + c0) + BN_EPS);
        float s1 = __ldg(bg + c0 + 1) * rsqrtf(__ldg(bv + c0 + 1) + BN_EPS);
        float mu0 = __ldg(bm + c0), mu1 = __ldg(bm + c0 + 1);
        float be0 = __ldg(bb + c0), be1 = __ldg(bb + c0 + 1);
        float bi0 = __ldg(b1 + c0), bi1 = __ldg(b1 + c0 + 1);
#pragma unroll
        for (int mt = 0; mt < 4; mt++) {
            int r0 = block_m + wm * 64 + mt * 16 + gq;
#pragma unroll
            for (int h = 0; h < 2; h++) {
                int r = r0 + h * 8;
                if (r < N_NODES) {
                    float v0 = acc[mt][nt][h * 2 + 0] + bi0;
                    float v1 = acc[mt][nt][h * 2 + 1] + bi1;
                    v0 = fmaxf((v0 - mu0) * s0 + be0, 0.f);
                    v1 = fmaxf((v1 - mu1) * s1 + be1, 0.f);
                    g_h1[(size_t)r * HID + c0] = __uint_as_float(tf32r(v0));
                    g_h1[(size_t)r * HID + c0 + 1] = __uint_as_float(tf32r(v1));
                }
            }
        }
    }
}

// ---------------------------------------------------------------------------
// K4: GEMM2 [50000,256]x[256,40] TF32 mma, cp.async 2-stage (R12 proven).
//     CTA 128x40, 8 warps, warp m16 x 5 n8, K chunk 32. Writes g_z only.
// ---------------------------------------------------------------------------
__global__ void __launch_bounds__(256)
gemm2_kernel() {
    __shared__ __align__(16) unsigned sA[2][128][36];
    __shared__ __align__(16) unsigned sB[2][32][44];
    int tid = threadIdx.x;
    int warp = tid >> 5, lane = tid & 31;
    int gq = lane >> 2, tg = lane & 3;
    int block_m = blockIdx.x * 128;

    int a_row[4], a_c4[4], a_sz[4];
    const float* a_gp0[4];
#pragma unroll
    for (int i = 0; i < 4; i++) {
        int f4 = tid + i * 256;
        a_row[i] = f4 >> 3;
        a_c4[i] = f4 & 7;
        int gr = block_m + a_row[i];
        a_sz[i] = (gr < N_NODES) ? 16 : 0;
        a_gp0[i] = g_h1 + (size_t)min(gr, N_NODES - 1) * HID + a_c4[i] * 4;
    }
    int b_k[2], b_c4[2], b_on[2];
#pragma unroll
    for (int i = 0; i < 2; i++) {
        int f4 = tid + i * 256;
        b_on[i] = (f4 < 320);
        int ff = b_on[i] ? f4 : 0;
        b_k[i] = ff / 10;
        b_c4[i] = ff - b_k[i] * 10;
    }

#define G2_ISSUE(chunk, buf)                                                     \
    {                                                                            \
        int kk_ = (chunk) * 32;                                                  \
        _Pragma("unroll")                                                        \
        for (int i = 0; i < 4; i++)                                              \
            cp_async16(smem_u32(&sA[(buf)][a_row[i]][a_c4[i] * 4]),              \
                       a_gp0[i] + kk_, a_sz[i]);                                 \
        _Pragma("unroll")                                                        \
        for (int i = 0; i < 2; i++)                                              \
            if (b_on[i])                                                         \
                cp_async16(smem_u32(&sB[(buf)][b_k[i]][b_c4[i] * 4]),            \
                           g_w2tf + (size_t)(kk_ + b_k[i]) * NCLS + b_c4[i] * 4, \
                           16);                                                  \
        cp_commit();                                                             \
    }

    float acc[5][4];
#pragma unroll
    for (int nt = 0; nt < 5; nt++)
#pragma unroll
        for (int r = 0; r < 4; r++) acc[nt][r] = 0.f;

    G2_ISSUE(0, 0);

    const int NITER = HID / 32;
#pragma unroll
    for (int it = 0; it < NITER; it++) {
        if (it < NITER - 1) {
            G2_ISSUE(it + 1, (it + 1) & 1);
            cp_wait<1>();
        } else {
            cp_wait<0>();
        }
        __syncthreads();
        int p = it & 1;
#pragma unroll
        for (int k8 = 0; k8 < 4; k8++) {
            int kb = k8 * 8;
            unsigned afr[4];
            int r = warp * 16;
            afr[0] = sA[p][r + gq][kb + tg];
            afr[1] = sA[p][r + gq + 8][kb + tg];
            afr[2] = sA[p][r + gq][kb + tg + 4];
            afr[3] = sA[p][r + gq + 8][kb + tg + 4];
#pragma unroll
            for (int nt = 0; nt < 5; nt++) {
                unsigned bfr[2];
                int c = nt * 8 + gq;
                bfr[0] = sB[p][kb + tg][c];
                bfr[1] = sB[p][kb + tg + 4][c];
                mma_tf32(acc[nt], afr, bfr);
            }
        }
        __syncthreads();
    }
#undef G2_ISSUE

#pragma unroll
    for (int nt = 0; nt < 5; nt++) {
        int c0 = nt * 8 + tg * 2;
        int r0 = block_m + warp * 16 + gq;
#pragma unroll
        for (int h = 0; h < 2; h++) {
            int r = r0 + h * 8;
            if (r < N_NODES) {
                g_z[(size_t)r * NCLS + c0] = acc[nt][h * 2 + 0];
                g_z[(size_t)r * NCLS + c0 + 1] = acc[nt][h * 2 + 1];
            }
        }
    }
}

// ---------------------------------------------------------------------------
// K5: gather in logit space + self term + bias. Unrolled x2.
// ---------------------------------------------------------------------------
__global__ void gather40_kernel(const float* __restrict__ b2,
                                float* __restrict__ out) {
    int t = blockIdx.x * blockDim.x + threadIdx.x;
    int node = t / (NCLS / 4);
    if (node >= N_NODES) return;
    int chunk = t - node * (NCLS / 4);
    float4 acc = *(const float4*)(g_z + (size_t)node * NCLS + chunk * 4);
    int beg = g_roff[node];
    int end = (node + 1 < N_NODES) ? g_roff[node + 1] : N_EDGES;
    int j = beg;
    for (; j + 1 < end; j += 2) {
        int s0 = __ldg(g_eidx + j);
        int s1 = __ldg(g_eidx + j + 1);
        float4 v0 = *(const float4*)(g_z + (size_t)s0 * NCLS + chunk * 4);
        float4 v1 = *(const float4*)(g_z + (size_t)s1 * NCLS + chunk * 4);
        acc.x += v0.x; acc.y += v0.y; acc.z += v0.z; acc.w += v0.w;
        acc.x += v1.x; acc.y += v1.y; acc.z += v1.z; acc.w += v1.w;
    }
    if (j < end) {
        int s0 = __ldg(g_eidx + j);
        float4 v0 = *(const float4*)(g_z + (size_t)s0 * NCLS + chunk * 4);
        acc.x += v0.x; acc.y += v0.y; acc.z += v0.z; acc.w += v0.w;
    }
    acc.x += __ldg(b2 + chunk * 4 + 0);
    acc.y += __ldg(b2 + chunk * 4 + 1);
    acc.z += __ldg(b2 + chunk * 4 + 2);
    acc.w += __ldg(b2 + chunk * 4 + 3);
    *(float4*)(out + (size_t)node * NCLS + chunk * 4) = acc;
}

// ---------------------------------------------------------------------------
extern "C" void kernel_launch(void* const* d_in, const int* in_sizes, int n_in,
                              void* d_out, int out_size) {
    const float* x = (const float*)d_in[0];
    const int* ei = (const int*)d_in[1];   // int32 (jax x64-disabled)
    const float* bn0g = (const float*)d_in[2];
    const float* bn0b = (const float*)d_in[3];
    const float* bn0m = (const float*)d_in[4];
    const float* bn0v = (const float*)d_in[5];
    const float* W1 = (const float*)d_in[6];
    const float* b1 = (const float*)d_in[7];
    const float* bn1g = (const float*)d_in[8];
    const float* bn1b = (const float*)d_in[9];
    const float* bn1m = (const float*)d_in[10];
    const float* bn1v = (const float*)d_in[11];
    const float* W2 = (const float*)d_in[12];
    const float* b2 = (const float*)d_in[13];
    float* out = (float*)d_out;

    const int* src = ei;
    const int* dst = ei + N_EDGES;

    // K0: pre-round weights + zero deg
    convert_w_kernel<<<(N_NODES + 255) / 256, 256>>>(W1, W2);
    // K1: fused BN0 (-> g_h0, L2-warm) + degree histogram
    {
        int total = N_NODES * (F_IN / 4);
        bn0_hist_kernel<<<(total + 255) / 256, 256>>>(
            (const float4*)x, bn0g, bn0b, bn0m, bn0v, dst);
    }
    // CSR build (cont.)
    scan_block_kernel<<<N_SCAN_BLOCKS, SCAN_BLK>>>();
    scan_add_kernel<<<(N_NODES + 255) / 256, 256>>>();
    fill_kernel<<<(N_EDGES + 255) / 256, 256>>>(src, dst);
    // K2: gather aggregation (F=128) -> g_agg1 (tf32-rounded)
    {
        long long threads = (long long)N_NODES * 32;
        agg128_kernel<<<(int)((threads + 255) / 256), 256>>>();
    }
    // K3: GEMM1 (tf32 mma, 2-stage cp.async) + BN1 + ReLU -> g_h1
    {
        dim3 grid((N_NODES + 127) / 128, HID / 128);
        gemm1_kernel<<<grid, 256>>>(b1, bn1g, bn1b, bn1m, bn1v);
    }
    // K4: GEMM2 (tf32 mma, 2-stage cp.async) -> g_z
    gemm2_kernel<<<(N_NODES + 127) / 128, 256>>>();
    // K5: gather in logit space + self + bias -> out
    {
        long long threads = (long long)N_NODES * (NCLS / 4);
        gather40_kernel<<<(int)((threads + 255) / 256), 256>>>(b2, out);
    }
}